// round 14
// baseline (speedup 1.0000x reference)
#include <cuda_runtime.h>
#include <cstdint>

// EntailmentConeLoss: loss = 0.5*( mean_i E(p_i,cpos_i) + mean_{i,k} relu(MARGIN - E(p_i,cneg_{ik})) )
// E(p,c) = relu(acos(clip((|c|^2-|p|^2-|c-p|^2)/(2|p||c-p|+eps))) - asin(clip(BETA/(|p|+eps),0,1-eps)))
//
// R13 = R1's main body verbatim (best measured 44.5us: one warp/pair, serial rows,
// diff-form energy, libm acos/asin, shfl butterflies, no reg cap) + a NO-ACQUIRE tail:
// per-block red.release.gpu.add.u64 fixed-point accumulation (fire-and-forget, integer
// = bit-deterministic, release does NOT invalidate L1 -- the per-block acq_rel in
// R6-R11 cost ~5-9us of lost L1 proto reuse) + counter; only the single last block
// performs one ld.acquire to finalize.

#define C_CONST 100000
#define D_CONST 256
#define P_CONST 65536
#define K_CONST 4
#define BETA 0.1f
#define MARGIN 0.1f
#define EPS 1e-6f

#define WARPS_PER_BLOCK 8
#define THREADS_PER_BLOCK (WARPS_PER_BLOCK * 32)
#define NUM_BLOCKS (P_CONST / WARPS_PER_BLOCK)   // 8192

// fixed-point scale for block contributions (each <= ~2.4e-4; 8192 blocks -> sum < 2^63)
#define ACC_SCALE 4503599627370496.0   // 2^52
#define ACC_INV   (1.0 / 4503599627370496.0)

__device__ unsigned long long g_acc;    // zero-init; last block resets each call
__device__ unsigned int       g_count;  // zero-init; last block resets each call

__device__ __forceinline__ float warp_sum(float v) {
    #pragma unroll
    for (int o = 16; o > 0; o >>= 1) v += __shfl_xor_sync(0xFFFFFFFFu, v, o);
    return v;
}

__global__ __launch_bounds__(THREADS_PER_BLOCK)
void cone_loss_kernel(const float* __restrict__ protos,
                      const int*   __restrict__ pairs,
                      const int*   __restrict__ neg_c,
                      float*       __restrict__ out) {
    const int wid  = threadIdx.x >> 5;
    const int lane = threadIdx.x & 31;
    const int pair = blockIdx.x * WARPS_PER_BLOCK + wid;   // one warp per pair

    __shared__ float s_warp[WARPS_PER_BLOCK];

    // ---- load p (1 row, 256 floats) into registers: 2x float4 per lane ----
    const int p_idx = pairs[2 * pair + 0];
    const int c_idx = pairs[2 * pair + 1];
    const float4* prow = reinterpret_cast<const float4*>(protos) + (size_t)p_idx * (D_CONST / 4);
    float4 pa = __ldg(&prow[lane]);
    float4 pb = __ldg(&prow[lane + 32]);

    float sp2_part = pa.x*pa.x + pa.y*pa.y + pa.z*pa.z + pa.w*pa.w
                   + pb.x*pb.x + pb.y*pb.y + pb.z*pb.z + pb.w*pb.w;
    float sp2 = warp_sum(sp2_part);
    float norm_p = sqrtf(sp2);

    // ---- process one c row (R1 verbatim) ----
    auto process_c = [&](int cidx) -> float {
        const float4* crow = reinterpret_cast<const float4*>(protos) + (size_t)cidx * (D_CONST / 4);
        float4 ca = __ldg(&crow[lane]);
        float4 cb = __ldg(&crow[lane + 32]);
        float sc2_part = ca.x*ca.x + ca.y*ca.y + ca.z*ca.z + ca.w*ca.w
                       + cb.x*cb.x + cb.y*cb.y + cb.z*cb.z + cb.w*cb.w;
        float dax = ca.x - pa.x, day = ca.y - pa.y, daz = ca.z - pa.z, daw = ca.w - pa.w;
        float dbx = cb.x - pb.x, dby = cb.y - pb.y, dbz = cb.z - pb.z, dbw = cb.w - pb.w;
        float sd2_part = dax*dax + day*day + daz*daz + daw*daw
                       + dbx*dbx + dby*dby + dbz*dbz + dbw*dbw;
        float sc2 = warp_sum(sc2_part);
        float sd2 = warp_sum(sd2_part);
        float num   = sc2 - sp2 - sd2;
        float denom = 2.0f * norm_p * sqrtf(sd2) + EPS;
        float cosang = num / denom;
        cosang = fminf(fmaxf(cosang, -1.0f + EPS), 1.0f - EPS);
        float ang = acosf(cosang);
        float sa  = BETA / (norm_p + EPS);
        sa = fminf(fmaxf(sa, 0.0f), 1.0f - EPS);
        float aperture = asinf(sa);
        return fmaxf(ang - aperture, 0.0f);
    };

    float e_pos = process_c(c_idx);

    float neg_sum = 0.0f;
    #pragma unroll
    for (int k = 0; k < K_CONST; k++) {
        int nc = neg_c[pair * K_CONST + k];
        float e = process_c(nc);
        neg_sum += fmaxf(MARGIN - e, 0.0f);
    }

    if (lane == 0) {
        s_warp[wid] = 0.5f * (e_pos    * (1.0f / (float)P_CONST)
                            + neg_sum  * (1.0f / ((float)P_CONST * (float)K_CONST)));
    }
    __syncthreads();

    // ---- tail: fire-and-forget release RED (no acquire -> L1 stays warm) ----
    __shared__ bool is_last;
    if (threadIdx.x == 0) {
        float bsum = 0.0f;
        #pragma unroll
        for (int w = 0; w < WARPS_PER_BLOCK; w++) bsum += s_warp[w];
        // fixed-point: integer adds commute -> bit-deterministic across replays
        unsigned long long q = (unsigned long long)__double2ll_rn((double)bsum * ACC_SCALE);
        asm volatile("red.release.gpu.global.add.u64 [%0], %1;"
                     :: "l"(&g_acc), "l"(q) : "memory");
        unsigned int old;
        asm volatile("atom.release.gpu.global.add.u32 %0, [%1], %2;"
                     : "=r"(old) : "l"(&g_count), "r"(1u) : "memory");
        is_last = (old == (unsigned int)(NUM_BLOCKS - 1));
    }
    __syncthreads();

    // ---- single last block finalizes (the ONLY acquire in the grid) ----
    if (is_last && threadIdx.x == 0) {
        unsigned long long total;
        asm volatile("ld.acquire.gpu.global.u64 %0, [%1];"
                     : "=l"(total) : "l"(&g_acc) : "memory");
        out[0] = (float)((double)total * ACC_INV);
        g_acc   = 0ull;   // reset for next graph replay (ordered by kernel boundary)
        g_count = 0u;
    }
}

extern "C" void kernel_launch(void* const* d_in, const int* in_sizes, int n_in,
                              void* d_out, int out_size) {
    const float* protos = (const float*)d_in[0];
    const int*   pairs  = (const int*)d_in[1];
    const int*   negc   = (const int*)d_in[2];
    float* out = (float*)d_out;

    cone_loss_kernel<<<NUM_BLOCKS, THREADS_PER_BLOCK>>>(protos, pairs, negc, out);
}

// round 15
// speedup vs baseline: 1.0825x; 1.0825x over previous
#include <cuda_runtime.h>
#include <cstdint>

// EntailmentConeLoss: loss = 0.5*( mean_i E(p_i,cpos_i) + mean_{i,k} relu(MARGIN - E(p_i,cneg_{ik})) )
// E(p,c) = relu(acos(clip((|c|^2-|p|^2-|c-p|^2)/(2|p||c-p|+eps))) - asin(clip(BETA/(|p|+eps),0,1-eps)))
//
// R14: R1's main body (best measured 44.5us) with the per-block partial store replaced
// by ONE fire-and-forget red.relaxed.gpu.add.u64 (fixed-point 2^52; integer adds commute
// -> bit-deterministic; no counter / no acquire / no in-kernel finalize -- every in-kernel
// tail variant measured 50.6-61us across R5-R13). A minimal 1-warp second kernel reads the
// accumulator (kernel boundary provides ordering), writes out[0], and resets.

#define C_CONST 100000
#define D_CONST 256
#define P_CONST 65536
#define K_CONST 4
#define BETA 0.1f
#define MARGIN 0.1f
#define EPS 1e-6f

#define WARPS_PER_BLOCK 8
#define THREADS_PER_BLOCK (WARPS_PER_BLOCK * 32)
#define NUM_BLOCKS (P_CONST / WARPS_PER_BLOCK)   // 8192

// fixed-point scale for block contributions (each <= ~2.4e-4; 8192 blocks -> sum < 2^63)
#define ACC_SCALE 4503599627370496.0   // 2^52
#define ACC_INV   (1.0 / 4503599627370496.0)

__device__ unsigned long long g_acc;   // zero-init; finalize kernel resets each call

__device__ __forceinline__ float warp_sum(float v) {
    #pragma unroll
    for (int o = 16; o > 0; o >>= 1) v += __shfl_xor_sync(0xFFFFFFFFu, v, o);
    return v;
}

__global__ __launch_bounds__(THREADS_PER_BLOCK)
void cone_loss_kernel(const float* __restrict__ protos,
                      const int*   __restrict__ pairs,
                      const int*   __restrict__ neg_c) {
    const int wid  = threadIdx.x >> 5;
    const int lane = threadIdx.x & 31;
    const int pair = blockIdx.x * WARPS_PER_BLOCK + wid;   // one warp per pair

    __shared__ float s_warp[WARPS_PER_BLOCK];

    // ---- load p (1 row, 256 floats) into registers: 2x float4 per lane ----
    const int p_idx = pairs[2 * pair + 0];
    const int c_idx = pairs[2 * pair + 1];
    const float4* prow = reinterpret_cast<const float4*>(protos) + (size_t)p_idx * (D_CONST / 4);
    float4 pa = __ldg(&prow[lane]);
    float4 pb = __ldg(&prow[lane + 32]);

    float sp2_part = pa.x*pa.x + pa.y*pa.y + pa.z*pa.z + pa.w*pa.w
                   + pb.x*pb.x + pb.y*pb.y + pb.z*pb.z + pb.w*pb.w;
    float sp2 = warp_sum(sp2_part);
    float norm_p = sqrtf(sp2);

    // ---- process one c row (R1 verbatim) ----
    auto process_c = [&](int cidx) -> float {
        const float4* crow = reinterpret_cast<const float4*>(protos) + (size_t)cidx * (D_CONST / 4);
        float4 ca = __ldg(&crow[lane]);
        float4 cb = __ldg(&crow[lane + 32]);
        float sc2_part = ca.x*ca.x + ca.y*ca.y + ca.z*ca.z + ca.w*ca.w
                       + cb.x*cb.x + cb.y*cb.y + cb.z*cb.z + cb.w*cb.w;
        float dax = ca.x - pa.x, day = ca.y - pa.y, daz = ca.z - pa.z, daw = ca.w - pa.w;
        float dbx = cb.x - pb.x, dby = cb.y - pb.y, dbz = cb.z - pb.z, dbw = cb.w - pb.w;
        float sd2_part = dax*dax + day*day + daz*daz + daw*daw
                       + dbx*dbx + dby*dby + dbz*dbz + dbw*dbw;
        float sc2 = warp_sum(sc2_part);
        float sd2 = warp_sum(sd2_part);
        float num   = sc2 - sp2 - sd2;
        float denom = 2.0f * norm_p * sqrtf(sd2) + EPS;
        float cosang = num / denom;
        cosang = fminf(fmaxf(cosang, -1.0f + EPS), 1.0f - EPS);
        float ang = acosf(cosang);
        float sa  = BETA / (norm_p + EPS);
        sa = fminf(fmaxf(sa, 0.0f), 1.0f - EPS);
        float aperture = asinf(sa);
        return fmaxf(ang - aperture, 0.0f);
    };

    float e_pos = process_c(c_idx);

    float neg_sum = 0.0f;
    #pragma unroll
    for (int k = 0; k < K_CONST; k++) {
        int nc = neg_c[pair * K_CONST + k];
        float e = process_c(nc);
        neg_sum += fmaxf(MARGIN - e, 0.0f);
    }

    if (lane == 0) {
        s_warp[wid] = 0.5f * (e_pos    * (1.0f / (float)P_CONST)
                            + neg_sum  * (1.0f / ((float)P_CONST * (float)K_CONST)));
    }
    __syncthreads();

    // ---- one fire-and-forget RED per block; nothing else ----
    if (threadIdx.x == 0) {
        float bsum = 0.0f;
        #pragma unroll
        for (int w = 0; w < WARPS_PER_BLOCK; w++) bsum += s_warp[w];
        unsigned long long q = (unsigned long long)__double2ll_rn((double)bsum * ACC_SCALE);
        asm volatile("red.relaxed.gpu.global.add.u64 [%0], %1;"
                     :: "l"(&g_acc), "l"(q) : "memory");
    }
}

// Minimal finalize: kernel boundary orders all REDs before this launch.
__global__ void finalize_kernel(float* __restrict__ out) {
    if (threadIdx.x == 0) {
        unsigned long long total = g_acc;
        out[0] = (float)((double)total * ACC_INV);
        g_acc = 0ull;   // reset for next graph replay
    }
}

extern "C" void kernel_launch(void* const* d_in, const int* in_sizes, int n_in,
                              void* d_out, int out_size) {
    const float* protos = (const float*)d_in[0];
    const int*   pairs  = (const int*)d_in[1];
    const int*   negc   = (const int*)d_in[2];
    float* out = (float*)d_out;

    cone_loss_kernel<<<NUM_BLOCKS, THREADS_PER_BLOCK>>>(protos, pairs, negc);
    finalize_kernel<<<1, 32>>>(out);
}